// round 1
// baseline (speedup 1.0000x reference)
#include <cuda_runtime.h>
#include <cuda_bf16.h>
#include <cstdint>

#define D 128
#define MAXN 100000

// Scratch (static device globals — no allocation at launch time)
__device__ float g_h[(size_t)MAXN * D];     // GEMM output / scatter source
__device__ float g_agg[(size_t)MAXN * D];   // aggregation buffer (layer 1)
__device__ float g_dinv[MAXN];
__device__ int   g_deg[MAXN];

// ---------------------------------------------------------------------------
// Degree / normalization
// ---------------------------------------------------------------------------
__global__ void zero_deg_kernel(int n) {
    int i = blockIdx.x * blockDim.x + threadIdx.x;
    if (i < n) g_deg[i] = 0;
}

__global__ void count_deg_kernel(const int* __restrict__ col, int E) {
    int e = blockIdx.x * blockDim.x + threadIdx.x;
    if (e < E) atomicAdd(&g_deg[col[e]], 1);
}

__global__ void dinv_kernel(int n) {
    int i = blockIdx.x * blockDim.x + threadIdx.x;
    if (i < n) g_dinv[i] = rsqrtf((float)g_deg[i] + 1.0f);
}

// ---------------------------------------------------------------------------
// GEMM: Y[n,128] = act(X[n,128]) @ W[128,128]
// Block: 128 threads, tile = 16 rows x 128 cols. Thread computes 4x4.
// W chunked through smem (2 x 64 k-rows), x tile resident in smem.
// ---------------------------------------------------------------------------
__global__ __launch_bounds__(128) void gemm128_kernel(
    const float* __restrict__ X, const float* __restrict__ W,
    float* __restrict__ Y, int n, int apply_relu) {
    __shared__ __align__(16) float xs[16][D];   // [row][k]  8 KB
    __shared__ __align__(16) float ws[64][D];   // [k][col] 32 KB

    const int t    = threadIdx.x;
    const int rq   = t >> 5;      // 0..3 -> rows rq*4 .. rq*4+3
    const int cq   = t & 31;      // 0..31 -> cols cq*4 .. cq*4+3
    const int row0 = blockIdx.x * 16;

    // Load x tile (coalesced, conflict-free: consecutive k per lane)
#pragma unroll
    for (int i = 0; i < 16; ++i) {
        int r = row0 + i;
        float v = (r < n) ? X[(size_t)r * D + t] : 0.0f;
        if (apply_relu) v = fmaxf(v, 0.0f);
        xs[i][t] = v;
    }

    float acc[4][4] = {};

    for (int kc = 0; kc < 2; ++kc) {
        __syncthreads();
        // Load 64x128 W chunk: 2048 float4, 16 per thread, coalesced
        const float4* wsrc = (const float4*)(W + (size_t)kc * 64 * D);
        float4* wdst = (float4*)ws;
#pragma unroll
        for (int i = 0; i < 16; ++i) wdst[i * 128 + t] = wsrc[i * 128 + t];
        __syncthreads();

#pragma unroll 4
        for (int k = 0; k < 64; k += 4) {
            float xr[4][4];
#pragma unroll
            for (int i = 0; i < 4; ++i) {
                float4 xv = *(const float4*)&xs[rq * 4 + i][kc * 64 + k];
                xr[i][0] = xv.x; xr[i][1] = xv.y; xr[i][2] = xv.z; xr[i][3] = xv.w;
            }
#pragma unroll
            for (int kk = 0; kk < 4; ++kk) {
                float4 wv = *(const float4*)&ws[k + kk][cq * 4];
#pragma unroll
                for (int i = 0; i < 4; ++i) {
                    acc[i][0] += xr[i][kk] * wv.x;
                    acc[i][1] += xr[i][kk] * wv.y;
                    acc[i][2] += xr[i][kk] * wv.z;
                    acc[i][3] += xr[i][kk] * wv.w;
                }
            }
        }
    }

#pragma unroll
    for (int i = 0; i < 4; ++i) {
        int r = row0 + rq * 4 + i;
        if (r < n) {
            float4 o = make_float4(acc[i][0], acc[i][1], acc[i][2], acc[i][3]);
            *(float4*)&Y[(size_t)r * D + cq * 4] = o;
        }
    }
}

// ---------------------------------------------------------------------------
// agg[n][c] = dinv[n]^2 * h[n][c] + b[c]   (self-loop term + bias, also
// initializes every output element so the later scatter can accumulate)
// ---------------------------------------------------------------------------
__global__ void init_agg_kernel(const float* __restrict__ h,
                                const float* __restrict__ b,
                                float* __restrict__ out, int n) {
    int idx = blockIdx.x * blockDim.x + threadIdx.x;   // over n * 32 float4s
    if (idx >= n * (D / 4)) return;
    int node = idx >> 5;
    int c4   = idx & 31;
    float di = g_dinv[node];
    float s  = di * di;
    float4 hv = ((const float4*)h)[idx];
    float4 bv = ((const float4*)b)[c4];
    float4 o = make_float4(fmaf(hv.x, s, bv.x), fmaf(hv.y, s, bv.y),
                           fmaf(hv.z, s, bv.z), fmaf(hv.w, s, bv.w));
    ((float4*)out)[idx] = o;
}

// ---------------------------------------------------------------------------
// Scatter: warp per edge. agg[col] += dinv[row]*dinv[col] * h[row]
// 512B coalesced gather per edge, 32x red.global.add.v4.f32 (vectorized,
// no return — L2 RMW, target buffer is L2-resident).
// ---------------------------------------------------------------------------
__global__ __launch_bounds__(256) void scatter_kernel(
    const float* __restrict__ h, const int* __restrict__ row,
    const int* __restrict__ col, float* __restrict__ agg, int E) {
    long long gtid = (long long)blockIdx.x * blockDim.x + threadIdx.x;
    int e = (int)(gtid >> 5);
    if (e >= E) return;
    int lane = threadIdx.x & 31;
    int r = __ldg(&row[e]);
    int c = __ldg(&col[e]);
    float coef = g_dinv[r] * g_dinv[c];
    float4 v = ((const float4*)(h + (size_t)r * D))[lane];
    float* dst = agg + (size_t)c * D + (lane << 2);
    asm volatile("red.global.add.v4.f32 [%0], {%1, %2, %3, %4};"
                 :: "l"(dst), "f"(v.x * coef), "f"(v.y * coef),
                    "f"(v.z * coef), "f"(v.w * coef)
                 : "memory");
}

// ---------------------------------------------------------------------------
extern "C" void kernel_launch(void* const* d_in, const int* in_sizes, int n_in,
                              void* d_out, int out_size) {
    const float* x  = (const float*)d_in[0];
    const int*   ei = (const int*)d_in[1];
    const float* W1 = (const float*)d_in[2];
    const float* b1 = (const float*)d_in[3];
    const float* W2 = (const float*)d_in[4];
    const float* b2 = (const float*)d_in[5];
    float* out = (float*)d_out;

    int n = in_sizes[0] / D;
    int E = in_sizes[1] / 2;
    const int* row = ei;        // edge_index[0]
    const int* col = ei + E;    // edge_index[1]

    float* h;   cudaGetSymbolAddress((void**)&h,   g_h);
    float* agg; cudaGetSymbolAddress((void**)&agg, g_agg);

    int nb256  = (n + 255) / 256;
    int eb256  = (E + 255) / 256;
    int gblk   = (n + 15) / 16;
    int initb  = (n * (D / 4) + 255) / 256;
    int scatb  = (E + 7) / 8;   // 32 threads per edge, 256/block

    // normalization
    zero_deg_kernel<<<nb256, 256>>>(n);
    count_deg_kernel<<<eb256, 256>>>(col, E);
    dinv_kernel<<<nb256, 256>>>(n);

    // layer 1
    gemm128_kernel<<<gblk, 128>>>(x, W1, h, n, 0);
    init_agg_kernel<<<initb, 256>>>(h, b1, agg, n);
    scatter_kernel<<<scatb, 256>>>(h, row, col, agg, E);

    // layer 2 (relu fused into GEMM input load)
    gemm128_kernel<<<gblk, 128>>>(agg, W2, h, n, 1);
    init_agg_kernel<<<initb, 256>>>(h, b2, out, n);
    scatter_kernel<<<scatb, 256>>>(h, row, col, out, E);
}

// round 3
// speedup vs baseline: 1.7531x; 1.7531x over previous
#include <cuda_runtime.h>
#include <cuda_bf16.h>
#include <cstdint>

#define D 128
#define MAXN 100000
#define MAXE 1600000

// Scratch (static device globals — no allocation at launch time)
__device__ float g_h[(size_t)MAXN * D];     // GEMM output / gather source
__device__ float g_agg[(size_t)MAXN * D];   // aggregation buffer (layer 1)
__device__ float g_dinv[MAXN];
__device__ int   g_deg[MAXN];
__device__ int   g_off[MAXN];               // CSR offsets (exclusive scan of deg)
__device__ int   g_cursor[MAXN];            // fill cursors
__device__ int   g_src[MAXE];               // CSR: source node per incoming edge
__device__ int   g_bsum[128];               // scan block sums
__device__ int   g_bbase[128];              // scan block bases

// ---------------------------------------------------------------------------
// Degree / normalization
// ---------------------------------------------------------------------------
__global__ void zero_deg_kernel(int n) {
    int i = blockIdx.x * blockDim.x + threadIdx.x;
    if (i < n) g_deg[i] = 0;
}

__global__ void count_deg_kernel(const int* __restrict__ col, int E) {
    int e = blockIdx.x * blockDim.x + threadIdx.x;
    if (e < E) atomicAdd(&g_deg[col[e]], 1);
}

__global__ void dinv_kernel(int n) {
    int i = blockIdx.x * blockDim.x + threadIdx.x;
    if (i < n) g_dinv[i] = rsqrtf((float)g_deg[i] + 1.0f);
}

// ---------------------------------------------------------------------------
// Exclusive scan of g_deg -> g_off (3-phase: block scan, scan of block sums,
// add base). Block size 1024, <=128 blocks for N<=131072.
// ---------------------------------------------------------------------------
__global__ __launch_bounds__(1024) void scan1_kernel(int n) {
    __shared__ int s[1024];
    int t = threadIdx.x;
    int i = blockIdx.x * 1024 + t;
    int v = (i < n) ? g_deg[i] : 0;
    s[t] = v;
    __syncthreads();
#pragma unroll
    for (int off = 1; off < 1024; off <<= 1) {
        int a = (t >= off) ? s[t - off] : 0;
        __syncthreads();
        s[t] += a;
        __syncthreads();
    }
    if (i < n) g_off[i] = s[t] - v;          // exclusive
    if (t == 1023) g_bsum[blockIdx.x] = s[1023];
}

__global__ void scan2_kernel(int nb) {
    __shared__ int s[128];
    int t = threadIdx.x;
    int v = (t < nb) ? g_bsum[t] : 0;
    s[t] = v;
    __syncthreads();
#pragma unroll
    for (int off = 1; off < 128; off <<= 1) {
        int a = (t >= off) ? s[t - off] : 0;
        __syncthreads();
        s[t] += a;
        __syncthreads();
    }
    g_bbase[t] = s[t] - v;                   // exclusive
}

__global__ __launch_bounds__(1024) void scan3_kernel(int n) {
    int i = blockIdx.x * 1024 + threadIdx.x;
    if (i < n) {
        int o = g_off[i] + g_bbase[blockIdx.x];
        g_off[i] = o;
        g_cursor[i] = o;
    }
}

// CSR fill: for each edge, place source node into destination's segment.
__global__ void fill_kernel(const int* __restrict__ row,
                            const int* __restrict__ col, int E) {
    int e = blockIdx.x * blockDim.x + threadIdx.x;
    if (e < E) {
        int p = atomicAdd(&g_cursor[col[e]], 1);
        g_src[p] = row[e];
    }
}

// ---------------------------------------------------------------------------
// GEMM: Y[n,128] = act(X[n,128]) @ W[128,128]
// Block: 128 threads, tile = 16 rows x 128 cols. Thread computes 4x4.
// ---------------------------------------------------------------------------
__global__ __launch_bounds__(128) void gemm128_kernel(
    const float* __restrict__ X, const float* __restrict__ W,
    float* __restrict__ Y, int n, int apply_relu) {
    __shared__ __align__(16) float xs[16][D];   // [row][k]  8 KB
    __shared__ __align__(16) float ws[64][D];   // [k][col] 32 KB

    const int t    = threadIdx.x;
    const int rq   = t >> 5;
    const int cq   = t & 31;
    const int row0 = blockIdx.x * 16;

#pragma unroll
    for (int i = 0; i < 16; ++i) {
        int r = row0 + i;
        float v = (r < n) ? X[(size_t)r * D + t] : 0.0f;
        if (apply_relu) v = fmaxf(v, 0.0f);
        xs[i][t] = v;
    }

    float acc[4][4] = {};

    for (int kc = 0; kc < 2; ++kc) {
        __syncthreads();
        const float4* wsrc = (const float4*)(W + (size_t)kc * 64 * D);
        float4* wdst = (float4*)ws;
#pragma unroll
        for (int i = 0; i < 16; ++i) wdst[i * 128 + t] = wsrc[i * 128 + t];
        __syncthreads();

#pragma unroll 4
        for (int k = 0; k < 64; k += 4) {
            float xr[4][4];
#pragma unroll
            for (int i = 0; i < 4; ++i) {
                float4 xv = *(const float4*)&xs[rq * 4 + i][kc * 64 + k];
                xr[i][0] = xv.x; xr[i][1] = xv.y; xr[i][2] = xv.z; xr[i][3] = xv.w;
            }
#pragma unroll
            for (int kk = 0; kk < 4; ++kk) {
                float4 wv = *(const float4*)&ws[k + kk][cq * 4];
#pragma unroll
                for (int i = 0; i < 4; ++i) {
                    acc[i][0] += xr[i][kk] * wv.x;
                    acc[i][1] += xr[i][kk] * wv.y;
                    acc[i][2] += xr[i][kk] * wv.z;
                    acc[i][3] += xr[i][kk] * wv.w;
                }
            }
        }
    }

#pragma unroll
    for (int i = 0; i < 4; ++i) {
        int r = row0 + rq * 4 + i;
        if (r < n) {
            float4 o = make_float4(acc[i][0], acc[i][1], acc[i][2], acc[i][3]);
            *(float4*)&Y[(size_t)r * D + cq * 4] = o;
        }
    }
}

// ---------------------------------------------------------------------------
// Gather: warp per destination node.
// out[c] = sum_{r in in(c)} dinv[r]*dinv[c]*h[r] + dinv[c]^2*h[c] + b
// Lane-chunked edge prefetch: each lane loads one edge's (src, dinv[src]),
// then the warp processes them via shfl broadcast with coalesced h loads.
// ---------------------------------------------------------------------------
__global__ __launch_bounds__(256) void gather_kernel(
    const float* __restrict__ h, const float* __restrict__ b,
    float* __restrict__ out, int n, int E) {
    int node = blockIdx.x * 8 + (threadIdx.x >> 5);
    if (node >= n) return;
    int lane = threadIdx.x & 31;

    float dc = g_dinv[node];
    const float4* h4 = (const float4*)h;

    int j    = g_off[node];
    int eend = (node + 1 < n) ? g_off[node + 1] : E;

    float4 acc = make_float4(0.f, 0.f, 0.f, 0.f);

    while (j < eend) {
        int cnt = min(32, eend - j);
        int r = 0; float dr = 0.f;
        if (lane < cnt) {
            r  = g_src[j + lane];
            dr = g_dinv[r];
        }
#pragma unroll 4
        for (int k = 0; k < cnt; ++k) {
            int   rk = __shfl_sync(0xffffffffu, r,  k);
            float cf = __shfl_sync(0xffffffffu, dr, k) * dc;
            float4 hv = h4[(size_t)rk * 32 + lane];
            acc.x = fmaf(cf, hv.x, acc.x);
            acc.y = fmaf(cf, hv.y, acc.y);
            acc.z = fmaf(cf, hv.z, acc.z);
            acc.w = fmaf(cf, hv.w, acc.w);
        }
        j += cnt;
    }

    // self-loop + bias
    float4 hv = h4[(size_t)node * 32 + lane];
    float4 bv = ((const float4*)b)[lane];
    float s2 = dc * dc;
    acc.x = fmaf(s2, hv.x, acc.x) + bv.x;
    acc.y = fmaf(s2, hv.y, acc.y) + bv.y;
    acc.z = fmaf(s2, hv.z, acc.z) + bv.z;
    acc.w = fmaf(s2, hv.w, acc.w) + bv.w;
    ((float4*)out)[(size_t)node * 32 + lane] = acc;
}

// ---------------------------------------------------------------------------
extern "C" void kernel_launch(void* const* d_in, const int* in_sizes, int n_in,
                              void* d_out, int out_size) {
    const float* x  = (const float*)d_in[0];
    const int*   ei = (const int*)d_in[1];
    const float* W1 = (const float*)d_in[2];
    const float* b1 = (const float*)d_in[3];
    const float* W2 = (const float*)d_in[4];
    const float* b2 = (const float*)d_in[5];
    float* out = (float*)d_out;

    int n = in_sizes[0] / D;
    int E = in_sizes[1] / 2;
    const int* row = ei;        // edge_index[0]
    const int* col = ei + E;    // edge_index[1]

    float* h;   cudaGetSymbolAddress((void**)&h,   g_h);
    float* agg; cudaGetSymbolAddress((void**)&agg, g_agg);

    int nb256 = (n + 255) / 256;
    int eb256 = (E + 255) / 256;
    int nb1k  = (n + 1023) / 1024;
    int gblk  = (n + 15) / 16;
    int gath  = (n + 7) / 8;

    // normalization + CSR build (once per call)
    zero_deg_kernel<<<nb256, 256>>>(n);
    count_deg_kernel<<<eb256, 256>>>(col, E);
    dinv_kernel<<<nb256, 256>>>(n);
    scan1_kernel<<<nb1k, 1024>>>(n);
    scan2_kernel<<<1, 128>>>(nb1k);
    scan3_kernel<<<nb1k, 1024>>>(n);
    fill_kernel<<<eb256, 256>>>(row, col, E);

    // layer 1
    gemm128_kernel<<<gblk, 128>>>(x, W1, h, n, 0);
    gather_kernel<<<gath, 256>>>(h, b1, agg, n, E);

    // layer 2 (relu fused into GEMM input load)
    gemm128_kernel<<<gblk, 128>>>(agg, W2, h, n, 1);
    gather_kernel<<<gath, 256>>>(h, b2, out, n, E);
}

// round 7
// speedup vs baseline: 2.2628x; 1.2907x over previous
#include <cuda_runtime.h>
#include <cuda_bf16.h>
#include <cstdint>

#define D 128
#define MAXN 100000
#define MAXE 1600000

// Scratch (static device globals — no allocation at launch time)
__device__ float g_h[(size_t)MAXN * D];     // GEMM output / gather source
__device__ float g_agg[(size_t)MAXN * D];   // aggregation buffer (layer 1)
__device__ float g_dinv[MAXN];
__device__ int   g_deg[MAXN];
__device__ int   g_off[MAXN];               // CSR offsets (exclusive scan of deg)
__device__ int   g_cursor[MAXN];            // fill cursors
__device__ int   g_src[MAXE];               // CSR: source node per incoming edge
__device__ int   g_bsum[128];               // scan block sums
__device__ int   g_bbase[128];              // scan block bases

// ---------------------------------------------------------------------------
// Degree / normalization
// ---------------------------------------------------------------------------
__global__ void zero_deg_kernel(int n) {
    int i = blockIdx.x * blockDim.x + threadIdx.x;
    if (i < n) g_deg[i] = 0;
}

__global__ void count_deg_kernel(const int* __restrict__ col, int E) {
    int e = blockIdx.x * blockDim.x + threadIdx.x;
    if (e < E) atomicAdd(&g_deg[col[e]], 1);
}

__global__ void dinv_kernel(int n) {
    int i = blockIdx.x * blockDim.x + threadIdx.x;
    if (i < n) g_dinv[i] = rsqrtf((float)g_deg[i] + 1.0f);
}

// ---------------------------------------------------------------------------
// Exclusive scan of g_deg -> g_off
// ---------------------------------------------------------------------------
__global__ __launch_bounds__(1024) void scan1_kernel(int n) {
    __shared__ int s[1024];
    int t = threadIdx.x;
    int i = blockIdx.x * 1024 + t;
    int v = (i < n) ? g_deg[i] : 0;
    s[t] = v;
    __syncthreads();
#pragma unroll
    for (int off = 1; off < 1024; off <<= 1) {
        int a = (t >= off) ? s[t - off] : 0;
        __syncthreads();
        s[t] += a;
        __syncthreads();
    }
    if (i < n) g_off[i] = s[t] - v;          // exclusive
    if (t == 1023) g_bsum[blockIdx.x] = s[1023];
}

__global__ void scan2_kernel(int nb) {
    __shared__ int s[128];
    int t = threadIdx.x;
    int v = (t < nb) ? g_bsum[t] : 0;
    s[t] = v;
    __syncthreads();
#pragma unroll
    for (int off = 1; off < 128; off <<= 1) {
        int a = (t >= off) ? s[t - off] : 0;
        __syncthreads();
        s[t] += a;
        __syncthreads();
    }
    g_bbase[t] = s[t] - v;                   // exclusive
}

__global__ __launch_bounds__(1024) void scan3_kernel(int n) {
    int i = blockIdx.x * 1024 + threadIdx.x;
    if (i < n) {
        int o = g_off[i] + g_bbase[blockIdx.x];
        g_off[i] = o;
        g_cursor[i] = o;
    }
}

__global__ void fill_kernel(const int* __restrict__ row,
                            const int* __restrict__ col, int E) {
    int e = blockIdx.x * blockDim.x + threadIdx.x;
    if (e < E) {
        int p = atomicAdd(&g_cursor[col[e]], 1);
        g_src[p] = row[e];
    }
}

// ---------------------------------------------------------------------------
// tf32 tensor-core GEMM: Y[n,128] = act(X[n,128]) @ W[128,128]
// Block: 256 threads (8 warps), tile 64 rows x 128 cols.
// Warp grid 4x2: warp computes 16 rows x 64 cols via mma.m16n8k8.tf32.
// X smem stride 132 (bank = gid*4+tig, conflict-free A frags)
// W smem stride 136 (bank = tig*8+gid, conflict-free B frags)
// ---------------------------------------------------------------------------
#define XS_STRIDE 132
#define WS_STRIDE 136
#define GEMM_SMEM_BYTES ((64 * XS_STRIDE + 128 * WS_STRIDE) * 4)

__device__ __forceinline__ uint32_t f2tf32(float v) {
    uint32_t u;
    asm("cvt.rna.tf32.f32 %0, %1;" : "=r"(u) : "f"(v));
    return u;
}

__global__ __launch_bounds__(256) void gemm_tf32_kernel(
    const float* __restrict__ X, const float* __restrict__ W,
    float* __restrict__ Y, int n, int apply_relu) {
    extern __shared__ uint32_t smem[];
    uint32_t* xs = smem;                       // [64][132]
    uint32_t* ws = smem + 64 * XS_STRIDE;      // [128][136]

    const int t      = threadIdx.x;
    const int lane   = t & 31;
    const int wid    = t >> 5;
    const int warp_m = wid >> 1;               // 0..3 -> rows warp_m*16
    const int warp_n = wid & 1;                // 0..1 -> cols warp_n*64
    const int gid    = lane >> 2;              // 0..7
    const int tig    = lane & 3;               // 0..3
    const int row0   = blockIdx.x * 64;

    // Load X tile (64 x 128), convert to tf32, optional relu
#pragma unroll
    for (int i = 0; i < 32; ++i) {
        int idx = i * 256 + t;
        int r = idx >> 7, c = idx & 127;
        float v = (row0 + r < n) ? X[(size_t)(row0 + r) * D + c] : 0.0f;
        if (apply_relu) v = fmaxf(v, 0.0f);
        xs[r * XS_STRIDE + c] = f2tf32(v);
    }
    // Load W (128 x 128), convert to tf32
#pragma unroll
    for (int i = 0; i < 64; ++i) {
        int idx = i * 256 + t;
        int r = idx >> 7, c = idx & 127;
        ws[r * WS_STRIDE + c] = f2tf32(W[idx]);
    }
    __syncthreads();

    float acc[8][4];
#pragma unroll
    for (int j = 0; j < 8; ++j)
#pragma unroll
        for (int q = 0; q < 4; ++q) acc[j][q] = 0.0f;

    const uint32_t* xb = xs + (warp_m * 16 + gid) * XS_STRIDE + tig;
    const uint32_t* wb = ws + tig * WS_STRIDE + warp_n * 64 + gid;

#pragma unroll
    for (int ks = 0; ks < 16; ++ks) {
        const int k0 = ks * 8;
        uint32_t a0 = xb[k0];
        uint32_t a1 = xb[8 * XS_STRIDE + k0];
        uint32_t a2 = xb[k0 + 4];
        uint32_t a3 = xb[8 * XS_STRIDE + k0 + 4];
#pragma unroll
        for (int j = 0; j < 8; ++j) {
            uint32_t b0 = wb[k0 * WS_STRIDE + j * 8];
            uint32_t b1 = wb[(k0 + 4) * WS_STRIDE + j * 8];
            asm volatile(
                "mma.sync.aligned.m16n8k8.row.col.f32.tf32.tf32.f32 "
                "{%0,%1,%2,%3}, {%4,%5,%6,%7}, {%8,%9}, {%0,%1,%2,%3};"
                : "+f"(acc[j][0]), "+f"(acc[j][1]), "+f"(acc[j][2]), "+f"(acc[j][3])
                : "r"(a0), "r"(a1), "r"(a2), "r"(a3), "r"(b0), "r"(b1));
        }
    }

    // Store: c0,c1 -> (row, col..col+1), c2,c3 -> (row+8, ...)
    int rA = row0 + warp_m * 16 + gid;
    int rB = rA + 8;
    int cb = warp_n * 64 + tig * 2;
#pragma unroll
    for (int j = 0; j < 8; ++j) {
        int c = cb + j * 8;
        if (rA < n) *(float2*)&Y[(size_t)rA * D + c] = make_float2(acc[j][0], acc[j][1]);
        if (rB < n) *(float2*)&Y[(size_t)rB * D + c] = make_float2(acc[j][2], acc[j][3]);
    }
}

// ---------------------------------------------------------------------------
// Gather: warp per destination node.
// out[c] = sum_{r in in(c)} dinv[r]*dinv[c]*h[r] + dinv[c]^2*h[c] + b
// ---------------------------------------------------------------------------
__global__ __launch_bounds__(256) void gather_kernel(
    const float* __restrict__ h, const float* __restrict__ b,
    float* __restrict__ out, int n, int E) {
    int node = blockIdx.x * 8 + (threadIdx.x >> 5);
    if (node >= n) return;
    int lane = threadIdx.x & 31;

    float dc = g_dinv[node];
    const float4* h4 = (const float4*)h;

    int j    = g_off[node];
    int eend = (node + 1 < n) ? g_off[node + 1] : E;

    float4 acc = make_float4(0.f, 0.f, 0.f, 0.f);

    while (j < eend) {
        int cnt = min(32, eend - j);
        int r = 0; float dr = 0.f;
        if (lane < cnt) {
            r  = g_src[j + lane];
            dr = g_dinv[r];
        }
#pragma unroll 4
        for (int k = 0; k < cnt; ++k) {
            int   rk = __shfl_sync(0xffffffffu, r,  k);
            float cf = __shfl_sync(0xffffffffu, dr, k) * dc;
            float4 hv = h4[(size_t)rk * 32 + lane];
            acc.x = fmaf(cf, hv.x, acc.x);
            acc.y = fmaf(cf, hv.y, acc.y);
            acc.z = fmaf(cf, hv.z, acc.z);
            acc.w = fmaf(cf, hv.w, acc.w);
        }
        j += cnt;
    }

    float4 hv = h4[(size_t)node * 32 + lane];
    float4 bv = ((const float4*)b)[lane];
    float s2 = dc * dc;
    acc.x = fmaf(s2, hv.x, acc.x) + bv.x;
    acc.y = fmaf(s2, hv.y, acc.y) + bv.y;
    acc.z = fmaf(s2, hv.z, acc.z) + bv.z;
    acc.w = fmaf(s2, hv.w, acc.w) + bv.w;
    ((float4*)out)[(size_t)node * 32 + lane] = acc;
}

// ---------------------------------------------------------------------------
extern "C" void kernel_launch(void* const* d_in, const int* in_sizes, int n_in,
                              void* d_out, int out_size) {
    const float* x  = (const float*)d_in[0];
    const int*   ei = (const int*)d_in[1];
    const float* W1 = (const float*)d_in[2];
    const float* b1 = (const float*)d_in[3];
    const float* W2 = (const float*)d_in[4];
    const float* b2 = (const float*)d_in[5];
    float* out = (float*)d_out;

    int n = in_sizes[0] / D;
    int E = in_sizes[1] / 2;
    const int* row = ei;        // edge_index[0]
    const int* col = ei + E;    // edge_index[1]

    float* h;   cudaGetSymbolAddress((void**)&h,   g_h);
    float* agg; cudaGetSymbolAddress((void**)&agg, g_agg);

    cudaFuncSetAttribute(gemm_tf32_kernel,
                         cudaFuncAttributeMaxDynamicSharedMemorySize,
                         GEMM_SMEM_BYTES);

    int nb256 = (n + 255) / 256;
    int eb256 = (E + 255) / 256;
    int nb1k  = (n + 1023) / 1024;
    int gblk  = (n + 63) / 64;
    int gath  = (n + 7) / 8;

    // normalization + CSR build (once per call)
    zero_deg_kernel<<<nb256, 256>>>(n);
    count_deg_kernel<<<eb256, 256>>>(col, E);
    dinv_kernel<<<nb256, 256>>>(n);
    scan1_kernel<<<nb1k, 1024>>>(n);
    scan2_kernel<<<1, 128>>>(nb1k);
    scan3_kernel<<<nb1k, 1024>>>(n);
    fill_kernel<<<eb256, 256>>>(row, col, E);

    // layer 1
    gemm_tf32_kernel<<<gblk, 256, GEMM_SMEM_BYTES>>>(x, W1, h, n, 0);
    gather_kernel<<<gath, 256>>>(h, b1, agg, n, E);

    // layer 2 (relu fused into GEMM input load)
    gemm_tf32_kernel<<<gblk, 256, GEMM_SMEM_BYTES>>>(agg, W2, h, n, 1);
    gather_kernel<<<gath, 256>>>(h, b2, out, n, E);
}

// round 10
// speedup vs baseline: 2.5159x; 1.1118x over previous
#include <cuda_runtime.h>
#include <cuda_bf16.h>
#include <cstdint>

#define D 128
#define MAXN 100000
#define MAXE 1600000

// Scratch (static device globals — no allocation at launch time)
__device__ float g_h[(size_t)MAXN * D];     // dinv-scaled GEMM output
__device__ float g_agg[(size_t)MAXN * D];   // aggregation buffer (layer 1)
__device__ float g_dinv[MAXN];
__device__ int   g_deg[MAXN];
__device__ int   g_off[MAXN];               // CSR offsets (exclusive scan of deg)
__device__ int   g_cursor[MAXN];            // fill cursors
__device__ int   g_src[MAXE];               // CSR: source node per incoming edge
__device__ int   g_bsum[128];               // scan block sums
__device__ int   g_bbase[128];              // scan block bases
__device__ float2 g_wpack[2][16 * 4 * D];   // pre-rounded, pre-packed W1/W2

__device__ __forceinline__ uint32_t f2tf32(float v) {
    uint32_t u;
    asm("cvt.rna.tf32.f32 %0, %1;" : "=r"(u) : "f"(v));
    return u;
}

// ---------------------------------------------------------------------------
// Degree / normalization
// ---------------------------------------------------------------------------
__global__ void zero_deg_kernel(int n) {
    int i = blockIdx.x * blockDim.x + threadIdx.x;
    if (i < n) g_deg[i] = 0;
}

__global__ void count_deg_kernel(const int* __restrict__ col, int E) {
    int e = blockIdx.x * blockDim.x + threadIdx.x;
    if (e < E) atomicAdd(&g_deg[col[e]], 1);
}

// ---------------------------------------------------------------------------
// Pre-pack W: RNA-round to tf32 and pack (k, k+4) pairs.
// wpack[w][(ks*4+tg)*128 + c] = (tf32(W[8ks+tg][c]), tf32(W[8ks+tg+4][c]))
// ---------------------------------------------------------------------------
__global__ void pack_w_kernel(const float* __restrict__ W1,
                              const float* __restrict__ W2) {
    int idx = blockIdx.x * blockDim.x + threadIdx.x;   // 0 .. 2*8192-1
    int w   = idx >> 13;
    int p   = idx & 8191;
    int ks  = p >> 9;
    int rem = p & 511;
    int tg  = rem >> 7, c = rem & 127;
    int k   = ks * 8 + tg;
    const float* W = w ? W2 : W1;
    float2 v;
    v.x = __uint_as_float(f2tf32(W[k * D + c]));
    v.y = __uint_as_float(f2tf32(W[(k + 4) * D + c]));
    g_wpack[w][p] = v;
}

// ---------------------------------------------------------------------------
// Exclusive scan of g_deg -> g_off (+ fused dinv computation)
// ---------------------------------------------------------------------------
__global__ __launch_bounds__(1024) void scan1_kernel(int n) {
    __shared__ int s[1024];
    int t = threadIdx.x;
    int i = blockIdx.x * 1024 + t;
    int v = (i < n) ? g_deg[i] : 0;
    if (i < n) g_dinv[i] = rsqrtf((float)v + 1.0f);
    s[t] = v;
    __syncthreads();
#pragma unroll
    for (int off = 1; off < 1024; off <<= 1) {
        int a = (t >= off) ? s[t - off] : 0;
        __syncthreads();
        s[t] += a;
        __syncthreads();
    }
    if (i < n) g_off[i] = s[t] - v;          // exclusive
    if (t == 1023) g_bsum[blockIdx.x] = s[1023];
}

__global__ void scan2_kernel(int nb) {
    __shared__ int s[128];
    int t = threadIdx.x;
    int v = (t < nb) ? g_bsum[t] : 0;
    s[t] = v;
    __syncthreads();
#pragma unroll
    for (int off = 1; off < 128; off <<= 1) {
        int a = (t >= off) ? s[t - off] : 0;
        __syncthreads();
        s[t] += a;
        __syncthreads();
    }
    g_bbase[t] = s[t] - v;                   // exclusive
}

__global__ __launch_bounds__(1024) void scan3_kernel(int n) {
    int i = blockIdx.x * 1024 + threadIdx.x;
    if (i < n) {
        int o = g_off[i] + g_bbase[blockIdx.x];
        g_off[i] = o;
        g_cursor[i] = o;
    }
}

__global__ void fill_kernel(const int* __restrict__ row,
                            const int* __restrict__ col, int E) {
    int e = blockIdx.x * blockDim.x + threadIdx.x;
    if (e < E) {
        int p = atomicAdd(&g_cursor[col[e]], 1);
        g_src[p] = row[e];
    }
}

// ---------------------------------------------------------------------------
// tf32 tensor-core GEMM: Y[r,128] = dinv[r] * (act(X[r,:]) @ W)
// Block: 256 threads (8 warps), tile 64 rows x 128 cols.
// Warp grid 4x2: warp computes 16 rows x 64 cols via mma.m16n8k8.tf32.
// X: cvt.rna in loader. W: pre-rounded pre-packed in g_wpack (no cvt here).
// X smem: [64][132] floats (bank = 4*gid+tig, conflict-free A frags).
// W smem: packed (k,k+4) float2 pairs, [64][132] float2
//         (bank = 8*tig+2*gid, conflict-free LDS.64 B frags).
// ---------------------------------------------------------------------------
#define XS_STRIDE 132
#define WSP_STRIDE 132
#define GEMM_SMEM_BYTES (64 * XS_STRIDE * 4 + 16 * 4 * WSP_STRIDE * 8)

__global__ __launch_bounds__(256) void gemm_tf32_kernel(
    const float* __restrict__ X, const float2* __restrict__ Wp,
    float* __restrict__ Y, int n, int apply_relu) {
    extern __shared__ float smem[];
    float*  xs  = smem;                              // [64][132]
    float2* wsp = (float2*)(smem + 64 * XS_STRIDE);  // [64][132] float2

    const int t      = threadIdx.x;
    const int lane   = t & 31;
    const int wid    = t >> 5;
    const int warp_m = wid >> 1;               // 0..3 -> rows warp_m*16
    const int warp_n = wid & 1;                // 0..1 -> cols warp_n*64
    const int gid    = lane >> 2;              // 0..7
    const int tig    = lane & 3;               // 0..3
    const int row0   = blockIdx.x * 64;

    // Load X tile (64 x 128), optional relu, RNA-round to tf32 bits
#pragma unroll
    for (int i = 0; i < 32; ++i) {
        int idx = i * 256 + t;
        int r = idx >> 7, c = idx & 127;
        float v = (row0 + r < n) ? X[(size_t)(row0 + r) * D + c] : 0.0f;
        if (apply_relu) v = fmaxf(v, 0.0f);
        xs[r * XS_STRIDE + c] = __uint_as_float(f2tf32(v));
    }
    // Copy pre-packed W (8192 float2), re-stride 128 -> 132
#pragma unroll
    for (int i = 0; i < 32; ++i) {
        int idx = i * 256 + t;
        int r = idx >> 7, c = idx & 127;
        wsp[r * WSP_STRIDE + c] = Wp[idx];
    }
    __syncthreads();

    float acc[8][4];
#pragma unroll
    for (int j = 0; j < 8; ++j)
#pragma unroll
        for (int q = 0; q < 4; ++q) acc[j][q] = 0.0f;

    const float* xb = xs + (warp_m * 16 + gid) * XS_STRIDE + tig;

#pragma unroll
    for (int ks = 0; ks < 16; ++ks) {
        const int k0 = ks * 8;
        uint32_t a0 = __float_as_uint(xb[k0]);
        uint32_t a1 = __float_as_uint(xb[8 * XS_STRIDE + k0]);
        uint32_t a2 = __float_as_uint(xb[k0 + 4]);
        uint32_t a3 = __float_as_uint(xb[8 * XS_STRIDE + k0 + 4]);
        const float2* wrow = wsp + (ks * 4 + tig) * WSP_STRIDE + warp_n * 64 + gid;
#pragma unroll
        for (int j = 0; j < 8; ++j) {
            float2 b = wrow[j * 8];
            asm volatile(
                "mma.sync.aligned.m16n8k8.row.col.f32.tf32.tf32.f32 "
                "{%0,%1,%2,%3}, {%4,%5,%6,%7}, {%8,%9}, {%0,%1,%2,%3};"
                : "+f"(acc[j][0]), "+f"(acc[j][1]), "+f"(acc[j][2]), "+f"(acc[j][3])
                : "r"(a0), "r"(a1), "r"(a2), "r"(a3),
                  "r"(__float_as_uint(b.x)), "r"(__float_as_uint(b.y)));
        }
    }

    // Epilogue: scale row by dinv, store.
    int rA = row0 + warp_m * 16 + gid;
    int rB = rA + 8;
    int cb = warp_n * 64 + tig * 2;
    float sA = (rA < n) ? g_dinv[rA] : 0.0f;
    float sB = (rB < n) ? g_dinv[rB] : 0.0f;
#pragma unroll
    for (int j = 0; j < 8; ++j) {
        int c = cb + j * 8;
        if (rA < n) *(float2*)&Y[(size_t)rA * D + c] =
            make_float2(acc[j][0] * sA, acc[j][1] * sA);
        if (rB < n) *(float2*)&Y[(size_t)rB * D + c] =
            make_float2(acc[j][2] * sB, acc[j][3] * sB);
    }
}

// ---------------------------------------------------------------------------
// Gather: warp per destination node. h is already dinv-scaled (hs = dinv*xW):
// out[c] = dinv[c] * ( sum_{r in in(c)} hs[r] + hs[c] ) + b
// Inner loop is pure accumulation — no per-edge coefficient.
// ---------------------------------------------------------------------------
__global__ __launch_bounds__(256) void gather_kernel(
    const float* __restrict__ h, const float* __restrict__ b,
    float* __restrict__ out, int n, int E) {
    int node = blockIdx.x * 8 + (threadIdx.x >> 5);
    if (node >= n) return;
    int lane = threadIdx.x & 31;

    float dc = g_dinv[node];
    const float4* h4 = (const float4*)h;

    int j    = g_off[node];
    int eend = (node + 1 < n) ? g_off[node + 1] : E;

    float4 acc = make_float4(0.f, 0.f, 0.f, 0.f);

    while (j < eend) {
        int cnt = min(32, eend - j);
        int r = 0;
        if (lane < cnt) r = g_src[j + lane];
#pragma unroll 4
        for (int k = 0; k < cnt; ++k) {
            int rk = __shfl_sync(0xffffffffu, r, k);
            float4 hv = h4[(size_t)rk * 32 + lane];
            acc.x += hv.x;
            acc.y += hv.y;
            acc.z += hv.z;
            acc.w += hv.w;
        }
        j += cnt;
    }

    // self-loop (hs[node]) + scale by dinv[node] + bias
    float4 hv = h4[(size_t)node * 32 + lane];
    float4 bv = ((const float4*)b)[lane];
    float4 o;
    o.x = fmaf(dc, acc.x + hv.x, bv.x);
    o.y = fmaf(dc, acc.y + hv.y, bv.y);
    o.z = fmaf(dc, acc.z + hv.z, bv.z);
    o.w = fmaf(dc, acc.w + hv.w, bv.w);
    ((float4*)out)[(size_t)node * 32 + lane] = o;
}

// ---------------------------------------------------------------------------
extern "C" void kernel_launch(void* const* d_in, const int* in_sizes, int n_in,
                              void* d_out, int out_size) {
    const float* x  = (const float*)d_in[0];
    const int*   ei = (const int*)d_in[1];
    const float* W1 = (const float*)d_in[2];
    const float* b1 = (const float*)d_in[3];
    const float* W2 = (const float*)d_in[4];
    const float* b2 = (const float*)d_in[5];
    float* out = (float*)d_out;

    int n = in_sizes[0] / D;
    int E = in_sizes[1] / 2;
    const int* row = ei;        // edge_index[0]
    const int* col = ei + E;    // edge_index[1]

    float* h;   cudaGetSymbolAddress((void**)&h,   g_h);
    float* agg; cudaGetSymbolAddress((void**)&agg, g_agg);
    float2* wp; cudaGetSymbolAddress((void**)&wp,  g_wpack);

    cudaFuncSetAttribute(gemm_tf32_kernel,
                         cudaFuncAttributeMaxDynamicSharedMemorySize,
                         GEMM_SMEM_BYTES);

    int nb256 = (n + 255) / 256;
    int eb256 = (E + 255) / 256;
    int nb1k  = (n + 1023) / 1024;
    int gblk  = (n + 63) / 64;
    int gath  = (n + 7) / 8;

    // normalization + CSR build + weight pre-pack (once per call)
    zero_deg_kernel<<<nb256, 256>>>(n);
    count_deg_kernel<<<eb256, 256>>>(col, E);
    pack_w_kernel<<<64, 256>>>(W1, W2);
    scan1_kernel<<<nb1k, 1024>>>(n);     // also computes dinv
    scan2_kernel<<<1, 128>>>(nb1k);
    scan3_kernel<<<nb1k, 1024>>>(n);
    fill_kernel<<<eb256, 256>>>(row, col, E);

    // layer 1
    gemm_tf32_kernel<<<gblk, 256, GEMM_SMEM_BYTES>>>(x, wp, h, n, 0);
    gather_kernel<<<gath, 256>>>(h, b1, agg, n, E);

    // layer 2 (relu fused into GEMM input load)
    gemm_tf32_kernel<<<gblk, 256, GEMM_SMEM_BYTES>>>(agg, wp + 8192, h, n, 1);
    gather_kernel<<<gath, 256>>>(h, b2, out, n, E);
}